// round 1
// baseline (speedup 1.0000x reference)
#include <cuda_runtime.h>
#include <math.h>

#define NP 1024
#define SPSZ 64
#define TPSZ 32
#define KCONST 0.6283185307179586f  // 2*pi/L, L=10

// ---- global scratch (no allocations allowed) ----
// sums layout: rowT0[1024*8], colT0[1024*8], row1,row2,row3[1024*32], col1,col2,col3[1024*32]
#define ROWT0 0
#define COLT0 8192
#define ROW1  16384
#define ROW2  49152
#define ROW3  81920
#define COL1  114688
#define COL2  147456
#define COL3  180224
#define SUMS_TOTAL 212992

__device__ float g_sums[SUMS_TOTAL];
__device__ float g_cs[NP * 3];
__device__ float g_sn[NP * 3];
__device__ float g_sp[NP * SPSZ];
__device__ float g_bias[SPSZ];

__device__ __forceinline__ float softplus_f(float x) {
    return __logf(1.0f + __expf(x));
}

// ---------------- init: zero sums + per-particle cos/sin ----------------
__global__ void init_kernel(const float* __restrict__ x) {
    int t = blockIdx.x * blockDim.x + threadIdx.x;
    if (t < SUMS_TOTAL) g_sums[t] = 0.0f;
    if (t < NP * 3) {
        float v = x[t] * KCONST;
        g_cs[t] = cosf(v);
        g_sn[t] = sinf(v);
    }
}

// ---------------- fused pairwise tp-stream kernel ----------------
// grid (32 jblocks, 4 iblocks), 256 threads = 8 warps.
// warp w handles rows ibase..ibase+31, lanes = 32 consecutive columns j.
__global__ __launch_bounds__(256, 1)
void pair_kernel(const float* __restrict__ tp_w0, const float* __restrict__ tp_b0,
                 const float* __restrict__ tp_w, const float* __restrict__ tp_b) {
    __shared__ float W0s[8][32];
    __shared__ float W1s[32][32];
    __shared__ float W2s[32][32];
    __shared__ float b0s[32], b1s[32], b2s[32];
    extern __shared__ float tiles[];  // per warp: t1[32*33], t2[32*33], t3[32*33], t0[32*9]

    int t = threadIdx.x;
    // cooperative weight load
    W0s[t >> 5][t & 31] = tp_w0[t];
    #pragma unroll
    for (int u = t; u < 1024; u += 256) {
        W1s[u >> 5][u & 31] = tp_w[u];
        W2s[u >> 5][u & 31] = tp_w[1024 + u];
    }
    if (t < 32) { b0s[t] = tp_b0[t]; b1s[t] = tp_b[t]; b2s[t] = tp_b[32 + t]; }
    __syncthreads();

    int lane = t & 31;
    int w = t >> 5;
    float* t1 = tiles + w * 3456;
    float* t2 = t1 + 1056;
    float* t3 = t2 + 1056;
    float* t0 = t3 + 1056;  // [32][9]

    int j = blockIdx.x * 32 + lane;
    float cj0 = g_cs[j * 3 + 0], cj1 = g_cs[j * 3 + 1], cj2 = g_cs[j * 3 + 2];
    float sj0 = g_sn[j * 3 + 0], sj1 = g_sn[j * 3 + 1], sj2 = g_sn[j * 3 + 2];

    float colT0[8];
    float col1[32], col2[32], col3[32];
    #pragma unroll
    for (int f = 0; f < 8; f++) colT0[f] = 0.0f;
    #pragma unroll
    for (int k = 0; k < 32; k++) { col1[k] = 0.0f; col2[k] = 0.0f; col3[k] = 0.0f; }

    int ibase = blockIdx.y * 256 + w * 32;

    for (int it = 0; it < 32; ++it) {
        int i = ibase + it;
        float ci0 = g_cs[i * 3 + 0], ci1 = g_cs[i * 3 + 1], ci2 = g_cs[i * 3 + 2];
        float si0 = g_sn[i * 3 + 0], si1 = g_sn[i * 3 + 1], si2 = g_sn[i * 3 + 2];

        // periodic displacement features via angle subtraction
        float f0 = ci0 * cj0 + si0 * sj0;
        float f1 = ci1 * cj1 + si1 * sj1;
        float f2 = ci2 * cj2 + si2 * sj2;
        float f3 = si0 * cj0 - ci0 * sj0;
        float f4 = si1 * cj1 - ci1 * sj1;
        float f5 = si2 * cj2 - ci2 * sj2;
        float ds = sqrtf(f3 * f3 + f4 * f4 + f5 * f5);
        float dc = sqrtf(f0 * f0 + f1 * f1 + f2 * f2);
        if (i == j) { ds = 0.0f; dc = 0.0f; }
        float feat[8] = {f0, f1, f2, f3, f4, f5, ds, dc};

        // layer 1: 8 -> 32
        float h1[32];
        #pragma unroll
        for (int k = 0; k < 32; k++) h1[k] = b0s[k];
        #pragma unroll
        for (int m = 0; m < 8; m++) {
            float fm = feat[m];
            #pragma unroll
            for (int k = 0; k < 32; k++) h1[k] += fm * W0s[m][k];
        }
        #pragma unroll
        for (int k = 0; k < 32; k++) h1[k] = softplus_f(h1[k]);

        // stage tp0 + h1 accumulation early to shorten h1 lifetime
        #pragma unroll
        for (int f = 0; f < 8; f++) { colT0[f] += feat[f]; t0[lane * 9 + f] = feat[f]; }

        // layer 2: residual 32 -> 32
        float h2[32];
        #pragma unroll
        for (int k = 0; k < 32; k++) h2[k] = b1s[k];
        #pragma unroll
        for (int m = 0; m < 32; m++) {
            float hm = h1[m];
            #pragma unroll
            for (int k = 0; k < 32; k++) h2[k] += hm * W1s[m][k];
        }
        #pragma unroll
        for (int k = 0; k < 32; k++) h2[k] = h1[k] + softplus_f(h2[k]);

        #pragma unroll
        for (int k = 0; k < 32; k++) { col1[k] += h1[k]; t1[lane * 33 + k] = h1[k]; }

        // layer 3: residual 32 -> 32
        float h3[32];
        #pragma unroll
        for (int k = 0; k < 32; k++) h3[k] = b2s[k];
        #pragma unroll
        for (int m = 0; m < 32; m++) {
            float hm = h2[m];
            #pragma unroll
            for (int k = 0; k < 32; k++) h3[k] += hm * W2s[m][k];
        }
        #pragma unroll
        for (int k = 0; k < 32; k++) h3[k] = h2[k] + softplus_f(h3[k]);

        #pragma unroll
        for (int k = 0; k < 32; k++) { col2[k] += h2[k]; t2[lane * 33 + k] = h2[k]; }
        #pragma unroll
        for (int k = 0; k < 32; k++) { col3[k] += h3[k]; t3[lane * 33 + k] = h3[k]; }

        __syncwarp();
        // row partial sums via smem transpose: lane owns feature f = lane
        float r1 = 0.0f, r2 = 0.0f, r3 = 0.0f;
        #pragma unroll
        for (int r = 0; r < 32; r++) {
            r1 += t1[r * 33 + lane];
            r2 += t2[r * 33 + lane];
            r3 += t3[r * 33 + lane];
        }
        atomicAdd(&g_sums[ROW1 + i * 32 + lane], r1);
        atomicAdd(&g_sums[ROW2 + i * 32 + lane], r2);
        atomicAdd(&g_sums[ROW3 + i * 32 + lane], r3);
        if (lane < 8) {
            float r0 = 0.0f;
            #pragma unroll
            for (int r = 0; r < 32; r++) r0 += t0[r * 9 + lane];
            atomicAdd(&g_sums[ROWT0 + i * 8 + lane], r0);
        }
        __syncwarp();
    }

    // flush per-lane column sums
    #pragma unroll
    for (int f = 0; f < 8; f++) atomicAdd(&g_sums[COLT0 + j * 8 + f], colT0[f]);
    #pragma unroll
    for (int k = 0; k < 32; k++) {
        atomicAdd(&g_sums[COL1 + j * 32 + k], col1[k]);
        atomicAdd(&g_sums[COL2 + j * 32 + k], col2[k]);
        atomicAdd(&g_sums[COL3 + j * 32 + k], col3[k]);
    }
}

// ---------------- sp stream ----------------
// layer 0: sp = softplus([0,0,0, rmT0, cmT0] @ sp_w0 + b0)  (only rows 9..24 matter)
__global__ void sp_layer0(const float* __restrict__ sp_w0, const float* __restrict__ sp_b0) {
    int i = blockIdx.x;
    int k = threadIdx.x;  // 64 threads
    __shared__ float rm[8], cm[8];
    if (k < 8)       rm[k]     = g_sums[ROWT0 + i * 8 + k] * (1.0f / 1024.0f);
    else if (k < 16) cm[k - 8] = g_sums[COLT0 + i * 8 + (k - 8)] * (1.0f / 1024.0f);
    __syncthreads();
    float acc = sp_b0[k];
    #pragma unroll
    for (int m = 0; m < 8; m++) acc += rm[m] * sp_w0[(9 + m) * 64 + k];
    #pragma unroll
    for (int m = 0; m < 8; m++) acc += cm[m] * sp_w0[(17 + m) * 64 + k];
    g_sp[i * 64 + k] = softplus_f(acc);
}

// fold up/dn means of sp into bias' for the next layer
__global__ void meanbias_kernel(const float* __restrict__ w, const float* __restrict__ b) {
    __shared__ float part[512];
    __shared__ float up[64], dn[64];
    int t = threadIdx.x;              // 512 threads
    int m = t & 63, g = t >> 6;       // g in 0..7, 128 rows each
    float s = 0.0f;
    int r0 = g * 128;
    #pragma unroll 8
    for (int r = 0; r < 128; r++) s += g_sp[(r0 + r) * 64 + m];
    part[t] = s;
    __syncthreads();
    if (t < 64) {
        up[t] = (part[t] + part[t + 64] + part[t + 128] + part[t + 192]) * (1.0f / 512.0f);
        dn[t] = (part[t + 256] + part[t + 320] + part[t + 384] + part[t + 448]) * (1.0f / 512.0f);
    }
    __syncthreads();
    if (t < 64) {
        float acc = b[t];
        #pragma unroll 8
        for (int m2 = 0; m2 < 64; m2++)
            acc += up[m2] * w[(64 + m2) * 64 + t] + dn[m2] * w[(128 + m2) * 64 + t];
        g_bias[t] = acc;
    }
}

// layers 1..3: sp += softplus([sp, up, dn, rm, cm] @ w + b); optionally fused final output
__global__ void sp_layer(const float* __restrict__ w, int rowoff, int coloff, int final_flag,
                         const float* __restrict__ x, const float* __restrict__ fin_w,
                         const float* __restrict__ fin_b, float* __restrict__ out) {
    int i = blockIdx.x;
    int k = threadIdx.x;  // 64 threads
    __shared__ float spRow[64];
    __shared__ float rm[32], cm[32];
    __shared__ float spNew[64];
    spRow[k] = g_sp[i * 64 + k];
    if (k < 32) rm[k] = g_sums[rowoff + i * 32 + k] * (1.0f / 1024.0f);
    else        cm[k - 32] = g_sums[coloff + i * 32 + (k - 32)] * (1.0f / 1024.0f);
    __syncthreads();
    float acc = g_bias[k];
    #pragma unroll 8
    for (int m = 0; m < 64; m++) acc += spRow[m] * w[m * 64 + k];
    #pragma unroll 8
    for (int m = 0; m < 32; m++) acc += rm[m] * w[(192 + m) * 64 + k];
    #pragma unroll 8
    for (int m = 0; m < 32; m++) acc += cm[m] * w[(224 + m) * 64 + k];
    float v = spRow[k] + softplus_f(acc);
    g_sp[i * 64 + k] = v;
    if (final_flag) {
        spNew[k] = v;
        __syncthreads();
        if (k < 3) {
            float o = fin_b[k] + x[i * 3 + k];
            #pragma unroll 8
            for (int m = 0; m < 64; m++) o += spNew[m] * fin_w[m * 3 + k];
            out[i * 3 + k] = o;
        }
    }
}

extern "C" void kernel_launch(void* const* d_in, const int* in_sizes, int n_in,
                              void* d_out, int out_size) {
    const float* x     = (const float*)d_in[0];
    const float* sp_w0 = (const float*)d_in[1];
    const float* sp_b0 = (const float*)d_in[2];
    const float* sp_w  = (const float*)d_in[3];   // (3,256,64)
    const float* sp_b  = (const float*)d_in[4];   // (3,64)
    const float* tp_w0 = (const float*)d_in[5];   // (8,32)
    const float* tp_b0 = (const float*)d_in[6];
    const float* tp_w  = (const float*)d_in[7];   // (2,32,32)
    const float* tp_b  = (const float*)d_in[8];   // (2,32)
    const float* fin_w = (const float*)d_in[9];   // (64,3)
    const float* fin_b = (const float*)d_in[10];
    float* out = (float*)d_out;

    const int pair_smem = 8 * 3456 * (int)sizeof(float);  // 110592 B
    cudaFuncSetAttribute(pair_kernel, cudaFuncAttributeMaxDynamicSharedMemorySize, pair_smem);

    init_kernel<<<(SUMS_TOTAL + 255) / 256, 256>>>(x);
    pair_kernel<<<dim3(32, 4), 256, pair_smem>>>(tp_w0, tp_b0, tp_w, tp_b);

    sp_layer0<<<NP, 64>>>(sp_w0, sp_b0);

    meanbias_kernel<<<1, 512>>>(sp_w + 0 * 16384, sp_b + 0 * 64);
    sp_layer<<<NP, 64>>>(sp_w + 0 * 16384, ROW1, COL1, 0, x, fin_w, fin_b, out);

    meanbias_kernel<<<1, 512>>>(sp_w + 1 * 16384, sp_b + 1 * 64);
    sp_layer<<<NP, 64>>>(sp_w + 1 * 16384, ROW2, COL2, 0, x, fin_w, fin_b, out);

    meanbias_kernel<<<1, 512>>>(sp_w + 2 * 16384, sp_b + 2 * 64);
    sp_layer<<<NP, 64>>>(sp_w + 2 * 16384, ROW3, COL3, 1, x, fin_w, fin_b, out);
}

// round 2
// speedup vs baseline: 1.0517x; 1.0517x over previous
#include <cuda_runtime.h>
#include <math.h>

#define NP 1024
#define SPSZ 64
#define TPSZ 32
#define KCONST 0.6283185307179586f  // 2*pi/L, L=10

typedef unsigned long long u64;

// ---- global scratch layout in g_sums ----
#define ROWT0 0
#define COLT0 8192
#define ROW1  16384
#define ROW2  49152
#define ROW3  81920
#define COL1  114688
#define COL2  147456
#define COL3  180224
#define SPSUM 212992            // 3 layers * 128 (up[64], dn[64])
#define SUMS_TOTAL (212992 + 3 * 128)

__device__ float g_sums[SUMS_TOTAL];
__device__ float g_cs[NP * 3];
__device__ float g_sn[NP * 3];
__device__ float g_sp[NP * SPSZ];
__device__ float g_bias[SPSZ];

__device__ __forceinline__ float softplus_f(float x) {
    return __logf(1.0f + __expf(x));
}

__device__ __forceinline__ void fma2(u64 &d, u64 a, u64 b) {
    asm("fma.rn.f32x2 %0, %1, %2, %0;" : "+l"(d) : "l"(a), "l"(b));
}
__device__ __forceinline__ u64 pack2(float x, float y) {
    u64 r; asm("mov.b64 %0, {%1, %2};" : "=l"(r) : "f"(x), "f"(y)); return r;
}
__device__ __forceinline__ void unpack2(u64 v, float &x, float &y) {
    asm("mov.b64 {%0, %1}, %2;" : "=f"(x), "=f"(y) : "l"(v));
}

// ---------------- init: zero sums + per-particle cos/sin ----------------
__global__ void init_kernel(const float* __restrict__ x) {
    int t = blockIdx.x * blockDim.x + threadIdx.x;
    if (t < SUMS_TOTAL) g_sums[t] = 0.0f;
    if (t < NP * 3) {
        float v = x[t] * KCONST;
        g_cs[t] = cosf(v);
        g_sn[t] = sinf(v);
    }
}

// ---------------- fused pairwise tp-stream kernel ----------------
// grid (32 jblocks, 4 iblocks), 256 threads = 8 warps.
// warp w handles rows ibase..ibase+31, lanes = 32 consecutive columns j.
__global__ __launch_bounds__(256, 1)
void pair_kernel(const float* __restrict__ tp_w0, const float* __restrict__ tp_b0,
                 const float* __restrict__ tp_w, const float* __restrict__ tp_b) {
    __shared__ ulonglong2 W0q[8][8];    // [m][kq], kq = 4 floats
    __shared__ ulonglong2 W1q[32][8];
    __shared__ ulonglong2 W2q[32][8];
    __shared__ u64 b0q[16], b1q[16], b2q[16];
    extern __shared__ float tiles[];  // per warp: t1[32*33], t2[32*33], t3[32*33], t0[32*9]

    int t = threadIdx.x;
    // cooperative weight load (aliased as row-major float [m][32])
    ((float*)W0q)[t] = tp_w0[t];
    float* W1f = (float*)W1q;
    float* W2f = (float*)W2q;
    #pragma unroll
    for (int u = t; u < 1024; u += 256) {
        W1f[u] = tp_w[u];
        W2f[u] = tp_w[1024 + u];
    }
    if (t < 16) {
        b0q[t] = pack2(tp_b0[2 * t], tp_b0[2 * t + 1]);
        b1q[t] = pack2(tp_b[2 * t], tp_b[2 * t + 1]);
        b2q[t] = pack2(tp_b[32 + 2 * t], tp_b[32 + 2 * t + 1]);
    }
    __syncthreads();

    int lane = t & 31;
    int w = t >> 5;
    float* t1 = tiles + w * 3456;
    float* t2 = t1 + 1056;
    float* t3 = t2 + 1056;
    float* t0 = t3 + 1056;  // [32][9]

    int j = blockIdx.x * 32 + lane;
    float cj0 = g_cs[j * 3 + 0], cj1 = g_cs[j * 3 + 1], cj2 = g_cs[j * 3 + 2];
    float sj0 = g_sn[j * 3 + 0], sj1 = g_sn[j * 3 + 1], sj2 = g_sn[j * 3 + 2];

    float colT0[8];
    float col1[32], col2[32], col3[32];
    #pragma unroll
    for (int f = 0; f < 8; f++) colT0[f] = 0.0f;
    #pragma unroll
    for (int k = 0; k < 32; k++) { col1[k] = 0.0f; col2[k] = 0.0f; col3[k] = 0.0f; }

    int ibase = blockIdx.y * 256 + w * 32;

    for (int it = 0; it < 32; ++it) {
        int i = ibase + it;
        float ci0 = g_cs[i * 3 + 0], ci1 = g_cs[i * 3 + 1], ci2 = g_cs[i * 3 + 2];
        float si0 = g_sn[i * 3 + 0], si1 = g_sn[i * 3 + 1], si2 = g_sn[i * 3 + 2];

        // periodic displacement features via angle subtraction
        float f0 = ci0 * cj0 + si0 * sj0;
        float f1 = ci1 * cj1 + si1 * sj1;
        float f2 = ci2 * cj2 + si2 * sj2;
        float f3 = si0 * cj0 - ci0 * sj0;
        float f4 = si1 * cj1 - ci1 * sj1;
        float f5 = si2 * cj2 - ci2 * sj2;
        float ds = sqrtf(f3 * f3 + f4 * f4 + f5 * f5);
        float dc = sqrtf(f0 * f0 + f1 * f1 + f2 * f2);
        if (i == j) { ds = 0.0f; dc = 0.0f; }
        float feat[8] = {f0, f1, f2, f3, f4, f5, ds, dc};

        // ---- layer 1: 8 -> 32 (packed f32x2) ----
        u64 acc[16];
        #pragma unroll
        for (int q = 0; q < 16; q++) acc[q] = b0q[q];
        #pragma unroll
        for (int m = 0; m < 8; m++) {
            u64 fm2 = pack2(feat[m], feat[m]);
            #pragma unroll
            for (int kq = 0; kq < 8; kq++) {
                ulonglong2 wq = W0q[m][kq];
                fma2(acc[2 * kq], fm2, wq.x);
                fma2(acc[2 * kq + 1], fm2, wq.y);
            }
        }
        float h1[32];
        #pragma unroll
        for (int q = 0; q < 16; q++) {
            float a, b; unpack2(acc[q], a, b);
            h1[2 * q] = softplus_f(a);
            h1[2 * q + 1] = softplus_f(b);
        }

        #pragma unroll
        for (int f = 0; f < 8; f++) { colT0[f] += feat[f]; t0[lane * 9 + f] = feat[f]; }

        // ---- layer 2: residual 32 -> 32 ----
        #pragma unroll
        for (int q = 0; q < 16; q++) acc[q] = b1q[q];
        #pragma unroll
        for (int m = 0; m < 32; m++) {
            u64 hm2 = pack2(h1[m], h1[m]);
            #pragma unroll
            for (int kq = 0; kq < 8; kq++) {
                ulonglong2 wq = W1q[m][kq];
                fma2(acc[2 * kq], hm2, wq.x);
                fma2(acc[2 * kq + 1], hm2, wq.y);
            }
        }
        float h2[32];
        #pragma unroll
        for (int q = 0; q < 16; q++) {
            float a, b; unpack2(acc[q], a, b);
            h2[2 * q] = h1[2 * q] + softplus_f(a);
            h2[2 * q + 1] = h1[2 * q + 1] + softplus_f(b);
        }

        #pragma unroll
        for (int k = 0; k < 32; k++) { col1[k] += h1[k]; t1[lane * 33 + k] = h1[k]; }

        // ---- layer 3: residual 32 -> 32 ----
        #pragma unroll
        for (int q = 0; q < 16; q++) acc[q] = b2q[q];
        #pragma unroll
        for (int m = 0; m < 32; m++) {
            u64 hm2 = pack2(h2[m], h2[m]);
            #pragma unroll
            for (int kq = 0; kq < 8; kq++) {
                ulonglong2 wq = W2q[m][kq];
                fma2(acc[2 * kq], hm2, wq.x);
                fma2(acc[2 * kq + 1], hm2, wq.y);
            }
        }
        float h3[32];
        #pragma unroll
        for (int q = 0; q < 16; q++) {
            float a, b; unpack2(acc[q], a, b);
            h3[2 * q] = h2[2 * q] + softplus_f(a);
            h3[2 * q + 1] = h2[2 * q + 1] + softplus_f(b);
        }

        #pragma unroll
        for (int k = 0; k < 32; k++) { col2[k] += h2[k]; t2[lane * 33 + k] = h2[k]; }
        #pragma unroll
        for (int k = 0; k < 32; k++) { col3[k] += h3[k]; t3[lane * 33 + k] = h3[k]; }

        __syncwarp();
        // row partial sums via smem transpose: lane owns feature f = lane
        float r1 = 0.0f, r2 = 0.0f, r3 = 0.0f;
        #pragma unroll
        for (int r = 0; r < 32; r++) {
            r1 += t1[r * 33 + lane];
            r2 += t2[r * 33 + lane];
            r3 += t3[r * 33 + lane];
        }
        atomicAdd(&g_sums[ROW1 + i * 32 + lane], r1);
        atomicAdd(&g_sums[ROW2 + i * 32 + lane], r2);
        atomicAdd(&g_sums[ROW3 + i * 32 + lane], r3);
        if (lane < 8) {
            float r0 = 0.0f;
            #pragma unroll
            for (int r = 0; r < 32; r++) r0 += t0[r * 9 + lane];
            atomicAdd(&g_sums[ROWT0 + i * 8 + lane], r0);
        }
        __syncwarp();
    }

    // flush per-lane column sums
    #pragma unroll
    for (int f = 0; f < 8; f++) atomicAdd(&g_sums[COLT0 + j * 8 + f], colT0[f]);
    #pragma unroll
    for (int k = 0; k < 32; k++) {
        atomicAdd(&g_sums[COL1 + j * 32 + k], col1[k]);
        atomicAdd(&g_sums[COL2 + j * 32 + k], col2[k]);
        atomicAdd(&g_sums[COL3 + j * 32 + k], col3[k]);
    }
}

// ---------------- sp stream ----------------
// layer 0: sp = softplus([0,0,0, rmT0, cmT0] @ sp_w0 + b0)  (only rows 9..24 matter)
// Also accumulates up/dn sums of the new sp into g_sums[SPSUM + 0*128 ...].
__global__ void sp_layer0(const float* __restrict__ sp_w0, const float* __restrict__ sp_b0) {
    int i = blockIdx.x;
    int k = threadIdx.x;  // 64 threads
    __shared__ float rm[8], cm[8];
    if (k < 8)       rm[k]     = g_sums[ROWT0 + i * 8 + k] * (1.0f / 1024.0f);
    else if (k < 16) cm[k - 8] = g_sums[COLT0 + i * 8 + (k - 8)] * (1.0f / 1024.0f);
    __syncthreads();
    float acc = sp_b0[k];
    #pragma unroll
    for (int m = 0; m < 8; m++) acc += rm[m] * sp_w0[(9 + m) * 64 + k];
    #pragma unroll
    for (int m = 0; m < 8; m++) acc += cm[m] * sp_w0[(17 + m) * 64 + k];
    float v = softplus_f(acc);
    g_sp[i * 64 + k] = v;
    atomicAdd(&g_sums[SPSUM + (i < 512 ? 0 : 64) + k], v);
}

// fold up/dn means of sp into bias' for the next layer (parallel, 256 threads)
__global__ void bias_kernel(const float* __restrict__ w, const float* __restrict__ b, int layer) {
    __shared__ float part[256];
    int t = threadIdx.x;
    int k = t & 63, p = t >> 6;   // p in 0..3, 32 m-rows each
    float acc = 0.0f;
    #pragma unroll 8
    for (int mm = 0; mm < 32; mm++) {
        int m2 = p * 32 + mm;     // 0..127 over [up(64), dn(64)]
        float mean = g_sums[SPSUM + layer * 128 + m2] * (1.0f / 512.0f);
        acc += mean * w[(64 + m2) * 64 + k];
    }
    part[t] = acc;
    __syncthreads();
    if (t < 64) g_bias[t] = b[t] + part[t] + part[t + 64] + part[t + 128] + part[t + 192];
}

// layers 1..3: sp += softplus([sp, up, dn, rm, cm] @ w + b'); optional sum accum + final output
__global__ void sp_layer(const float* __restrict__ w, int rowoff, int coloff,
                         int sumidx, int final_flag,
                         const float* __restrict__ x, const float* __restrict__ fin_w,
                         const float* __restrict__ fin_b, float* __restrict__ out) {
    int i = blockIdx.x;
    int k = threadIdx.x;  // 64 threads
    __shared__ float spRow[64];
    __shared__ float rm[32], cm[32];
    __shared__ float spNew[64];
    spRow[k] = g_sp[i * 64 + k];
    if (k < 32) rm[k] = g_sums[rowoff + i * 32 + k] * (1.0f / 1024.0f);
    else        cm[k - 32] = g_sums[coloff + i * 32 + (k - 32)] * (1.0f / 1024.0f);
    __syncthreads();
    float acc = g_bias[k];
    #pragma unroll 8
    for (int m = 0; m < 64; m++) acc += spRow[m] * w[m * 64 + k];
    #pragma unroll 8
    for (int m = 0; m < 32; m++) acc += rm[m] * w[(192 + m) * 64 + k];
    #pragma unroll 8
    for (int m = 0; m < 32; m++) acc += cm[m] * w[(224 + m) * 64 + k];
    float v = spRow[k] + softplus_f(acc);
    g_sp[i * 64 + k] = v;
    if (sumidx >= 0) atomicAdd(&g_sums[SPSUM + sumidx * 128 + (i < 512 ? 0 : 64) + k], v);
    if (final_flag) {
        spNew[k] = v;
        __syncthreads();
        if (k < 3) {
            float o = fin_b[k] + x[i * 3 + k];
            #pragma unroll 8
            for (int m = 0; m < 64; m++) o += spNew[m] * fin_w[m * 3 + k];
            out[i * 3 + k] = o;
        }
    }
}

extern "C" void kernel_launch(void* const* d_in, const int* in_sizes, int n_in,
                              void* d_out, int out_size) {
    const float* x     = (const float*)d_in[0];
    const float* sp_w0 = (const float*)d_in[1];
    const float* sp_b0 = (const float*)d_in[2];
    const float* sp_w  = (const float*)d_in[3];   // (3,256,64)
    const float* sp_b  = (const float*)d_in[4];   // (3,64)
    const float* tp_w0 = (const float*)d_in[5];   // (8,32)
    const float* tp_b0 = (const float*)d_in[6];
    const float* tp_w  = (const float*)d_in[7];   // (2,32,32)
    const float* tp_b  = (const float*)d_in[8];   // (2,32)
    const float* fin_w = (const float*)d_in[9];   // (64,3)
    const float* fin_b = (const float*)d_in[10];
    float* out = (float*)d_out;

    const int pair_smem = 8 * 3456 * (int)sizeof(float);  // 110592 B
    cudaFuncSetAttribute(pair_kernel, cudaFuncAttributeMaxDynamicSharedMemorySize, pair_smem);

    init_kernel<<<(SUMS_TOTAL + 255) / 256, 256>>>(x);
    pair_kernel<<<dim3(32, 4), 256, pair_smem>>>(tp_w0, tp_b0, tp_w, tp_b);

    sp_layer0<<<NP, 64>>>(sp_w0, sp_b0);

    bias_kernel<<<1, 256>>>(sp_w + 0 * 16384, sp_b + 0 * 64, 0);
    sp_layer<<<NP, 64>>>(sp_w + 0 * 16384, ROW1, COL1, 1, 0, x, fin_w, fin_b, out);

    bias_kernel<<<1, 256>>>(sp_w + 1 * 16384, sp_b + 1 * 64, 1);
    sp_layer<<<NP, 64>>>(sp_w + 1 * 16384, ROW2, COL2, 2, 0, x, fin_w, fin_b, out);

    bias_kernel<<<1, 256>>>(sp_w + 2 * 16384, sp_b + 2 * 64, 2);
    sp_layer<<<NP, 64>>>(sp_w + 2 * 16384, ROW3, COL3, -1, 1, x, fin_w, fin_b, out);
}